// round 2
// baseline (speedup 1.0000x reference)
#include <cuda_runtime.h>
#include <cstddef>

// 7x7 VALID conv, 4096x4096 fp32 in -> 4090x4090 fp32 out, + bias.
// Block: 16x16 threads. Each block computes a 128(w) x 32(h) output tile.
// Each thread computes 2 rows x 8 cols = 16 outputs.
// Input tile in smem: (32+6) x (128+6) floats, padded to 136 cols for float4 stores.

#define IN_W 4096
#define IN_H 4096
#define OUT_W 4090
#define OUT_H 4090

#define TILE_W 128      // output cols per block
#define TILE_H 32       // output rows per block
#define SM_H (TILE_H + 6)   // 38
#define SM_W 136            // 134 needed, padded to multiple of 4

__global__ __launch_bounds__(256)
void conv7x7_kernel(const float* __restrict__ x,
                    const float* __restrict__ w,
                    const float* __restrict__ bias,
                    float* __restrict__ out)
{
    __shared__ float tile[SM_H][SM_W];
    __shared__ float ws[49];
    __shared__ float bs;

    const int tx = threadIdx.x;           // 0..15
    const int ty = threadIdx.y;           // 0..15
    const int tid = ty * 16 + tx;         // 0..255

    const int bx = blockIdx.x * TILE_W;   // output col base
    const int by = blockIdx.y * TILE_H;   // output row base

    if (tid < 49) ws[tid] = w[tid];
    if (tid == 49) bs = bias[0];

    // ---- Load input tile (38 rows x 136 cols, float4 granularity) ----
    // Needed input region: rows [by, by+37], cols [bx, bx+133]; pad/zero outside.
    #pragma unroll 1
    for (int i = tid; i < SM_H * (SM_W / 4); i += 256) {
        const int r  = i / (SM_W / 4);
        const int c4 = i - r * (SM_W / 4);
        const int gy = by + r;
        const int gx = bx + c4 * 4;
        float4 v = make_float4(0.f, 0.f, 0.f, 0.f);
        if (gy < IN_H) {
            const float* row = x + (size_t)gy * IN_W;
            if (gx + 4 <= IN_W) {
                v = *reinterpret_cast<const float4*>(row + gx);
            } else if (gx < IN_W) {
                v.x = row[gx];
                if (gx + 1 < IN_W) v.y = row[gx + 1];
                if (gx + 2 < IN_W) v.z = row[gx + 2];
                // gx+3 >= IN_W here
            }
        }
        *reinterpret_cast<float4*>(&tile[r][c4 * 4]) = v;
    }
    __syncthreads();

    // ---- Compute: 2 output rows x 8 output cols per thread ----
    const int tx8 = tx * 8;        // thread's col offset within tile
    const int ry  = ty * 2;        // thread's first output row within tile

    float acc0[8] = {0.f, 0.f, 0.f, 0.f, 0.f, 0.f, 0.f, 0.f};
    float acc1[8] = {0.f, 0.f, 0.f, 0.f, 0.f, 0.f, 0.f, 0.f};

    // Slide over the 8 input rows this thread touches. Row r feeds:
    //   acc0 with weight-row r     (for r in 0..6)
    //   acc1 with weight-row r-1   (for r in 1..7)
    #pragma unroll
    for (int r = 0; r < 8; r++) {
        float seg[16];
        {
            const float* srow = &tile[ry + r][tx8];
            *reinterpret_cast<float4*>(&seg[0])  = *reinterpret_cast<const float4*>(srow + 0);
            *reinterpret_cast<float4*>(&seg[4])  = *reinterpret_cast<const float4*>(srow + 4);
            *reinterpret_cast<float4*>(&seg[8])  = *reinterpret_cast<const float4*>(srow + 8);
            *reinterpret_cast<float4*>(&seg[12]) = *reinterpret_cast<const float4*>(srow + 12);
        }
        if (r < 7) {
            #pragma unroll
            for (int dx = 0; dx < 7; dx++) {
                const float wt = ws[r * 7 + dx];
                #pragma unroll
                for (int v = 0; v < 8; v++)
                    acc0[v] = fmaf(seg[dx + v], wt, acc0[v]);
            }
        }
        if (r >= 1) {
            #pragma unroll
            for (int dx = 0; dx < 7; dx++) {
                const float wt = ws[(r - 1) * 7 + dx];
                #pragma unroll
                for (int v = 0; v < 8; v++)
                    acc1[v] = fmaf(seg[dx + v], wt, acc1[v]);
            }
        }
    }

    // ---- Store with edge guards ----
    const float bv = bs;
    const int ox  = bx + tx8;
    const int oy0 = by + ry;

    if (oy0 < OUT_H) {
        float* orow = out + (size_t)oy0 * OUT_W;
        #pragma unroll
        for (int v = 0; v < 8; v++)
            if (ox + v < OUT_W) orow[ox + v] = acc0[v] + bv;
    }
    if (oy0 + 1 < OUT_H) {
        float* orow = out + (size_t)(oy0 + 1) * OUT_W;
        #pragma unroll
        for (int v = 0; v < 8; v++)
            if (ox + v < OUT_W) orow[ox + v] = acc1[v] + bv;
    }
}

extern "C" void kernel_launch(void* const* d_in, const int* in_sizes, int n_in,
                              void* d_out, int out_size)
{
    const float* x    = (const float*)d_in[0];
    const float* w    = (const float*)d_in[1];
    const float* bias = (const float*)d_in[2];
    float* out = (float*)d_out;

    dim3 block(16, 16);
    dim3 grid((OUT_W + TILE_W - 1) / TILE_W,   // 32
              (OUT_H + TILE_H - 1) / TILE_H);  // 128
    conv7x7_kernel<<<grid, block>>>(x, w, bias, out);
}

// round 3
// speedup vs baseline: 1.2287x; 1.2287x over previous
#include <cuda_runtime.h>
#include <cstddef>

// 7x7 VALID conv, 4096x4096 fp32 -> 4090x4090 fp32, + bias.
// Block 16x16 = 256 threads; tile 128(w) x 64(h) outputs; thread: 4 rows x 8 cols.
// Inner loop uses packed fma.rn.f32x2 (FFMA2): adjacent output columns share one
// packed accumulator; weights are broadcast as (w,w) u64 pairs from smem.

#define IN_W 4096
#define IN_H 4096
#define OUT_W 4090
#define OUT_H 4090

#define TILE_W 128
#define TILE_H 64
#define SM_H (TILE_H + 6)   // 70
#define SM_W 136            // 134 needed, padded to /4

typedef unsigned long long u64;

__device__ __forceinline__ u64 pk(float a, float b) {
    u64 r;
    asm("mov.b64 %0, {%1, %2};" : "=l"(r) : "f"(a), "f"(b));
    return r;
}
__device__ __forceinline__ void upk(u64 v, float &a, float &b) {
    asm("mov.b64 {%0, %1}, %2;" : "=f"(a), "=f"(b) : "l"(v));
}
__device__ __forceinline__ void fma2(u64 &d, u64 a, u64 b) {
    asm("fma.rn.f32x2 %0, %1, %2, %3;" : "=l"(d) : "l"(a), "l"(b), "l"(d));
}

__global__ __launch_bounds__(256)
void conv7x7_kernel(const float* __restrict__ x,
                    const float* __restrict__ w,
                    const float* __restrict__ bias,
                    float* __restrict__ out)
{
    __shared__ float tile[SM_H][SM_W];
    __shared__ u64   wp[49];
    __shared__ float bs;

    const int tx = threadIdx.x;         // 0..15
    const int ty = threadIdx.y;         // 0..15
    const int tid = ty * 16 + tx;

    const int bx = blockIdx.x * TILE_W;
    const int by = blockIdx.y * TILE_H;

    if (tid < 49) { float wv = w[tid]; wp[tid] = pk(wv, wv); }
    if (tid == 49) bs = bias[0];

    // ---- Load input tile (70 x 136 floats, float4 granularity) ----
    #pragma unroll 1
    for (int i = tid; i < SM_H * (SM_W / 4); i += 256) {
        const int r  = i / (SM_W / 4);
        const int c4 = i - r * (SM_W / 4);
        const int gy = by + r;
        const int gx = bx + c4 * 4;
        float4 v = make_float4(0.f, 0.f, 0.f, 0.f);
        if (gy < IN_H) {
            const float* row = x + (size_t)gy * IN_W;
            if (gx + 4 <= IN_W) {
                v = *reinterpret_cast<const float4*>(row + gx);
            } else if (gx < IN_W) {
                v.x = row[gx];
                if (gx + 1 < IN_W) v.y = row[gx + 1];
                if (gx + 2 < IN_W) v.z = row[gx + 2];
            }
        }
        *reinterpret_cast<float4*>(&tile[r][c4 * 4]) = v;
    }
    __syncthreads();

    // ---- Compute: 4 output rows x 8 cols per thread, packed FFMA2 ----
    const int tx8 = tx * 8;
    const int ry  = ty * 4;

    // acc[ar][v2] covers output (row ry+ar, cols tx8+2*v2, tx8+2*v2+1)
    u64 acc[4][4];
    #pragma unroll
    for (int a = 0; a < 4; a++)
        #pragma unroll
        for (int b = 0; b < 4; b++)
            acc[a][b] = 0ull;   // bit pattern == (0.f, 0.f)

    #pragma unroll
    for (int r = 0; r < 10; r++) {
        float seg[16];
        {
            const float* srow = &tile[ry + r][tx8];
            *reinterpret_cast<float4*>(&seg[0])  = *reinterpret_cast<const float4*>(srow + 0);
            *reinterpret_cast<float4*>(&seg[4])  = *reinterpret_cast<const float4*>(srow + 4);
            *reinterpret_cast<float4*>(&seg[8])  = *reinterpret_cast<const float4*>(srow + 8);
            *reinterpret_cast<float4*>(&seg[12]) = *reinterpret_cast<const float4*>(srow + 12);
        }
        // Pairs P[k] = (seg[k], seg[k+1]), k = 0..13
        u64 P[14];
        #pragma unroll
        for (int k = 0; k < 14; k++) P[k] = pk(seg[k], seg[k + 1]);

        // Input row (ry+r) feeds acc row ar with weight row kr = r - ar
        #pragma unroll
        for (int ar = 0; ar < 4; ar++) {
            const int kr = r - ar;
            if (kr >= 0 && kr <= 6) {
                #pragma unroll
                for (int dx = 0; dx < 7; dx++) {
                    const u64 wv = wp[kr * 7 + dx];
                    #pragma unroll
                    for (int v2 = 0; v2 < 4; v2++)
                        fma2(acc[ar][v2], P[dx + 2 * v2], wv);
                }
            }
        }
    }

    // ---- Store (float2, 8B-aligned: row stride 4090*4 B and ox even) ----
    const float bv = bs;
    #pragma unroll
    for (int ar = 0; ar < 4; ar++) {
        const int oy = by + ry + ar;
        if (oy < OUT_H) {
            float* orow = out + (size_t)oy * OUT_W;
            #pragma unroll
            for (int v2 = 0; v2 < 4; v2++) {
                const int ox = tx8 + bx + 2 * v2;
                if (ox < OUT_W) {
                    float lo, hi;
                    upk(acc[ar][v2], lo, hi);
                    float2 o; o.x = lo + bv; o.y = hi + bv;
                    *reinterpret_cast<float2*>(orow + ox) = o;
                }
            }
        }
    }
}

extern "C" void kernel_launch(void* const* d_in, const int* in_sizes, int n_in,
                              void* d_out, int out_size)
{
    const float* x    = (const float*)d_in[0];
    const float* w    = (const float*)d_in[1];
    const float* bias = (const float*)d_in[2];
    float* out = (float*)d_out;

    dim3 block(16, 16);
    dim3 grid((OUT_W + TILE_W - 1) / TILE_W,   // 32
              (OUT_H + TILE_H - 1) / TILE_H);  // 64
    conv7x7_kernel<<<grid, block>>>(x, w, bias, out);
}